// round 14
// baseline (speedup 1.0000x reference)
#include <cuda_runtime.h>
#include <cuda_fp16.h>
#include <cstdint>

// ===========================================================================
// TransducerJoint via mma.sync fp16 (HMMA):
//   logits[b,t,u,v] = tanh(E[bt,:] + P[b,u,:]) @ W_out + b_out
//   B=4 T=200 U=100 ENC=512 PRED=512 JOINT=640 VOCAB=1024; M=80000 N=1024 K=640
//
// R14: R13 falsified the barrier-overhead model (BK 32->64 was neutral).
// Attack SMEM fragment traffic instead: warp tile 64x64 (ma=4, na=8) at
// 256 threads -> 4 B LDS per MMA (was 6), -38% LDS issue slots. Same MMA
// count, same accumulation order (rel_err must repeat exactly).
// proj: 32x64 tiles (500 CTAs) to cut its latency-bound 46us.
// ===========================================================================

#define B_DIM 4
#define T_DIM 200
#define U_DIM 100
#define ENC_DIM 512
#define JOINT_DIM 640
#define VOCAB 1024

__device__ float g_E[B_DIM * T_DIM * JOINT_DIM];   // [800,640]
__device__ float g_P[B_DIM * U_DIM * JOINT_DIM];   // [400,640]
// W_out fp16 fragments: [10 kchunks(64)][4 nblocks(256)] x 32KB
__device__ __align__(16) unsigned char g_Wf[10 * 4 * 32768];

// ---------------------------------------------------------------------------
// helpers
// ---------------------------------------------------------------------------
__device__ __forceinline__ uint32_t smem_u32(const void* p) {
    uint32_t a;
    asm("{ .reg .u64 t; cvta.to.shared.u64 t, %1; cvt.u32.u64 %0, t; }"
        : "=r"(a) : "l"(p));
    return a;
}
__device__ __forceinline__ float tanh_fast(float x) {
    float r; asm("tanh.approx.f32 %0, %1;" : "=f"(r) : "f"(x)); return r;
}
// pack two fp32 -> f16x2 (first arg -> LOW half = even-k element)
__device__ __forceinline__ uint32_t pack_h(float lo, float hi) {
    uint32_t r; asm("cvt.rn.f16x2.f32 %0, %1, %2;" : "=r"(r) : "f"(hi), "f"(lo));
    return r;
}
__device__ __forceinline__ void mma_f16(float* c, const uint4& a, const uint2& b) {
    asm volatile(
        "mma.sync.aligned.m16n8k16.row.col.f32.f16.f16.f32 "
        "{%0,%1,%2,%3}, {%4,%5,%6,%7}, {%8,%9}, {%0,%1,%2,%3};"
        : "+f"(c[0]), "+f"(c[1]), "+f"(c[2]), "+f"(c[3])
        : "r"(a.x), "r"(a.y), "r"(a.z), "r"(a.w), "r"(b.x), "r"(b.y));
}
#define CP_ASYNC16(dst, src) \
    asm volatile("cp.async.cg.shared.global [%0], [%1], 16;" \
                 :: "r"(dst), "l"(src) : "memory")
#define CP_COMMIT() asm volatile("cp.async.commit_group;" ::: "memory")
#define CP_WAIT0()  asm volatile("cp.async.wait_group 0;" ::: "memory")

// ---------------------------------------------------------------------------
// Stage 1+2 fused: z=0 -> E (M=800, +bias), z=1 -> P (M=400, no bias).
// R14: 32x64x16 tiles, 500 CTAs (was 64x64 / 260 CTAs, latency-bound).
// ---------------------------------------------------------------------------
__global__ __launch_bounds__(256)
void proj_kernel(const float* __restrict__ enc, const float* __restrict__ pred,
                 const float* __restrict__ W_enc, const float* __restrict__ W_pred,
                 const float* __restrict__ b_enc)
{
    const int z = blockIdx.z;
    const float* A    = z ? pred : enc;
    const float* W    = z ? W_pred : W_enc;
    const float* bias = z ? nullptr : b_enc;
    float* C          = z ? g_P : g_E;
    const int M       = z ? (B_DIM * U_DIM) : (B_DIM * T_DIM);

    const int BM = 32, BN = 64, BK = 16;
    const int m0 = blockIdx.y * BM;
    if (m0 >= M) return;
    const int n0 = blockIdx.x * BN;

    __shared__ float As[BK][BM];
    __shared__ float Bs[BK][BN];

    const int t  = threadIdx.x;
    const int tx = t & 15, ty = t >> 4;          // ty: 2 rows, tx: 4 cols
    const int arow = t >> 3, ak = (t & 7) << 1;  // 32 rows x 16k, float2 each
    const int brow = t >> 4, bcol = (t & 15) << 2;

    float acc[2][4];
#pragma unroll
    for (int i = 0; i < 2; i++)
#pragma unroll
        for (int j = 0; j < 4; j++) acc[i][j] = 0.f;

    for (int k0 = 0; k0 < ENC_DIM; k0 += BK) {
        float2 av = make_float2(0.f, 0.f);
        if (m0 + arow < M)
            av = *(const float2*)(A + (size_t)(m0 + arow) * ENC_DIM + k0 + ak);
        As[ak + 0][arow] = av.x;
        As[ak + 1][arow] = av.y;
        *(float4*)&Bs[brow][bcol] =
            *(const float4*)(W + (size_t)(k0 + brow) * JOINT_DIM + n0 + bcol);
        __syncthreads();
#pragma unroll
        for (int k = 0; k < BK; k++) {
            float a[2], b[4];
#pragma unroll
            for (int i = 0; i < 2; i++) a[i] = As[k][ty * 2 + i];
#pragma unroll
            for (int j = 0; j < 4; j++) b[j] = Bs[k][tx * 4 + j];
#pragma unroll
            for (int i = 0; i < 2; i++)
#pragma unroll
                for (int j = 0; j < 4; j++)
                    acc[i][j] = fmaf(a[i], b[j], acc[i][j]);
        }
        __syncthreads();
    }
    float bv[4] = {0.f, 0.f, 0.f, 0.f};
    if (bias) {
        float4 b4 = *(const float4*)(bias + n0 + tx * 4);
        bv[0] = b4.x; bv[1] = b4.y; bv[2] = b4.z; bv[3] = b4.w;
    }
#pragma unroll
    for (int i = 0; i < 2; i++) {
        int row = m0 + ty * 2 + i;
        if (row < M) {
            float4 v;
            v.x = acc[i][0] + bv[0]; v.y = acc[i][1] + bv[1];
            v.z = acc[i][2] + bv[2]; v.w = acc[i][3] + bv[3];
            *(float4*)(C + (size_t)row * JOINT_DIM + n0 + tx * 4) = v;
        }
    }
}

// ---------------------------------------------------------------------------
// Stage 2.5: W_out[640,1024] -> fp16 mma.sync B-fragment layout, BK=64.
// (unchanged from R13)
// ---------------------------------------------------------------------------
__global__ __launch_bounds__(256)
void wprep_kernel(const float* __restrict__ W)
{
    int id    = blockIdx.x * 256 + threadIdx.x;    // 0..163839
    int lane  = id & 31;
    int j     = (id >> 5) & 3;
    int natom = (id >> 7) & 31;
    int nbx   = (id >> 12) & 3;
    int kc    = id >> 14;                           // 0..9

    int n  = nbx * 256 + natom * 8 + (lane >> 2);
    int k0 = kc * 64 + j * 16 + (lane & 3) * 2;

    float w0 = W[(size_t)(k0 + 0) * VOCAB + n];
    float w1 = W[(size_t)(k0 + 1) * VOCAB + n];
    float w8 = W[(size_t)(k0 + 8) * VOCAB + n];
    float w9 = W[(size_t)(k0 + 9) * VOCAB + n];

    size_t blk  = (size_t)(kc * 4 + nbx) * 32768;
    size_t frag = (size_t)((natom * 4 + j) * 32 + lane) * 8;
    *(uint2*)(g_Wf + blk + frag) = make_uint2(pack_h(w0, w1), pack_h(w8, w9));
}

// ---------------------------------------------------------------------------
// Stage 3: fused joint GEMM, single fp16 MMA, BK=64, 256 threads / 8 warps.
// Grid (4, 625). CTA tile 128x256; warp grid 2(M) x 4(N); warp tile 64x64
// (ma=4, na=8). Double buffer: [A 16K | B 32K] x 2 = 96KB.
// A producer: warp wid owns atom pi=wid, all 4 j-phases, woven between MMAs.
// ---------------------------------------------------------------------------
#define BUF_BYTES 49152
#define SMEM_NEED 98304

__global__ __launch_bounds__(256, 1)
void joint_mma_kernel(const float* __restrict__ bout, float* __restrict__ out)
{
    extern __shared__ char smem[];

    const int t    = threadIdx.x;
    const int lane = t & 31;
    const int wid  = t >> 5;            // 0..7
    const int wy   = wid >> 2;          // 0..1  (M, 64 rows each)
    const int wx   = wid & 3;           // 0..3  (N, 64 cols each)
    const int g    = lane >> 2;
    const int tg   = lane & 3;
    const int m0   = blockIdx.y * 128;
    const int n0   = blockIdx.x * 256;
    const int bx   = blockIdx.x;

    // ---- A producer geometry: atom pi = wid (8 atoms = 128 rows)
    const int pi = wid;
    const int r0 = m0 + pi * 16 + g;
    const int r1 = r0 + 8;
    const int bt0 = r0 / U_DIM, u0 = r0 - bt0 * U_DIM, bb0 = bt0 / T_DIM;
    const int bt1 = r1 / U_DIM, u1 = r1 - bt1 * U_DIM, bb1 = bt1 / T_DIM;
    const float* E0 = g_E + (size_t)bt0 * JOINT_DIM;
    const float* P0 = g_P + (size_t)(bb0 * U_DIM + u0) * JOINT_DIM;
    const float* E1 = g_E + (size_t)bt1 * JOINT_DIM;
    const float* P1 = g_P + (size_t)(bb1 * U_DIM + u1) * JOINT_DIM;
    const int kbase = tg * 2;

    float acc[4][8][4];
#pragma unroll
    for (int ma = 0; ma < 4; ma++)
#pragma unroll
        for (int na = 0; na < 8; na++)
#pragma unroll
            for (int q = 0; q < 4; q++) acc[ma][na][q] = 0.f;

    // prefetch one j-phase (16 k-values across rows r0,r1)
    auto prefA = [&](int kc, int j, float2 (&e0)[2], float2 (&p0)[2],
                     float2 (&e1)[2], float2 (&p1)[2]) {
        const int off = kc * 64 + j * 16 + kbase;
        e0[0] = *(const float2*)(E0 + off);
        e0[1] = *(const float2*)(E0 + off + 8);
        p0[0] = *(const float2*)(P0 + off);
        p0[1] = *(const float2*)(P0 + off + 8);
        e1[0] = *(const float2*)(E1 + off);
        e1[1] = *(const float2*)(E1 + off + 8);
        p1[0] = *(const float2*)(P1 + off);
        p1[1] = *(const float2*)(P1 + off + 8);
    };
    auto storeA = [&](char* buf, int j, const float2 (&e0)[2],
                      const float2 (&p0)[2], const float2 (&e1)[2],
                      const float2 (&p1)[2]) {
        float x00 = tanh_fast(e0[0].x + p0[0].x);
        float x01 = tanh_fast(e0[0].y + p0[0].y);
        float x08 = tanh_fast(e0[1].x + p0[1].x);
        float x09 = tanh_fast(e0[1].y + p0[1].y);
        float x10 = tanh_fast(e1[0].x + p1[0].x);
        float x11 = tanh_fast(e1[0].y + p1[0].y);
        float x18 = tanh_fast(e1[1].x + p1[1].x);
        float x19 = tanh_fast(e1[1].y + p1[1].y);
        const int idx = (pi * 4 + j) * 32 + lane;
        ((uint4*)buf)[idx] = make_uint4(pack_h(x00, x01), pack_h(x10, x11),
                                        pack_h(x08, x09), pack_h(x18, x19));
    };
    auto issueB = [&](int kc, char* buf) {
        const char* src = (const char*)g_Wf + (size_t)(kc * 4 + bx) * 32768
                        + (size_t)t * 128;
        uint32_t dst = smem_u32(buf + 16384 + t * 128);
#pragma unroll
        for (int i = 0; i < 8; i++)
            CP_ASYNC16(dst + i * 16, src + i * 16);
    };
    // one MMA j-phase: 32 MMAs per warp
    auto mmaJ = [&](const char* cbuf, int j) {
        const uint4* Ah = (const uint4*)cbuf;
        const uint2* Bf = (const uint2*)(cbuf + 16384);
        uint2 bf[8];
#pragma unroll
        for (int na = 0; na < 8; na++)
            bf[na] = Bf[((wx * 8 + na) * 4 + j) * 32 + lane];
#pragma unroll
        for (int ma = 0; ma < 4; ma++) {
            const uint4 ah = Ah[((wy * 4 + ma) * 4 + j) * 32 + lane];
#pragma unroll
            for (int na = 0; na < 8; na++)
                mma_f16(acc[ma][na], ah, bf[na]);
        }
    };

    // ---- prologue: fill buffer 0 (two prefetch sets, pipelined)
    {
        issueB(0, smem);
        CP_COMMIT();
        float2 e0[2], p0[2], e1[2], p1[2];
        float2 f0[2], q0[2], f1[2], q1[2];
        prefA(0, 0, e0, p0, e1, p1);
        prefA(0, 1, f0, q0, f1, q1);
        storeA(smem, 0, e0, p0, e1, p1);
        prefA(0, 2, e0, p0, e1, p1);
        storeA(smem, 1, f0, q0, f1, q1);
        prefA(0, 3, f0, q0, f1, q1);
        storeA(smem, 2, e0, p0, e1, p1);
        storeA(smem, 3, f0, q0, f1, q1);
        CP_WAIT0();
    }
    __syncthreads();

#pragma unroll 1
    for (int kc = 0; kc < 10; kc++) {
        char* cbuf = smem + (kc & 1) * BUF_BYTES;
        char* nbuf = smem + ((kc + 1) & 1) * BUF_BYTES;
        const bool more = (kc < 9);

        float2 e0[2], p0[2], e1[2], p1[2];
        if (more) {
            issueB(kc + 1, nbuf);
            CP_COMMIT();
            prefA(kc + 1, 0, e0, p0, e1, p1);
        }
        mmaJ(cbuf, 0);
        if (more) {
            storeA(nbuf, 0, e0, p0, e1, p1);
            prefA(kc + 1, 1, e0, p0, e1, p1);
        }
        mmaJ(cbuf, 1);
        if (more) {
            storeA(nbuf, 1, e0, p0, e1, p1);
            prefA(kc + 1, 2, e0, p0, e1, p1);
        }
        mmaJ(cbuf, 2);
        if (more) {
            storeA(nbuf, 2, e0, p0, e1, p1);
            prefA(kc + 1, 3, e0, p0, e1, p1);
        }
        mmaJ(cbuf, 3);
        if (more) {
            storeA(nbuf, 3, e0, p0, e1, p1);
            CP_WAIT0();
        }
        __syncthreads();
    }

    // ---- epilogue: bias + streaming float2 stores
    float2 bias2[8];
#pragma unroll
    for (int na = 0; na < 8; na++)
        bias2[na] = *(const float2*)(bout + n0 + wx * 64 + na * 8 + tg * 2);

#pragma unroll
    for (int ma = 0; ma < 4; ma++) {
        const int ra = m0 + (wy * 4 + ma) * 16 + g;
        float* rowa = out + (size_t)ra * VOCAB + n0 + wx * 64;
        float* rowb = rowa + (size_t)8 * VOCAB;
#pragma unroll
        for (int na = 0; na < 8; na++) {
            float2 va, vb;
            va.x = acc[ma][na][0] + bias2[na].x;
            va.y = acc[ma][na][1] + bias2[na].y;
            vb.x = acc[ma][na][2] + bias2[na].x;
            vb.y = acc[ma][na][3] + bias2[na].y;
            __stcs((float2*)(rowa + na * 8 + tg * 2), va);
            __stcs((float2*)(rowb + na * 8 + tg * 2), vb);
        }
    }
}

// ---------------------------------------------------------------------------
// Launch. Inputs: 0 enc_out, 1 pred_out, 2 W_enc, 3 b_enc, 4 W_pred,
//                 5 W_out, 6 b_out.  Output fp32 [4,200,100,1024].
// ---------------------------------------------------------------------------
extern "C" void kernel_launch(void* const* d_in, const int* in_sizes, int n_in,
                              void* d_out, int out_size)
{
    const float* enc_out  = (const float*)d_in[0];
    const float* pred_out = (const float*)d_in[1];
    const float* W_enc    = (const float*)d_in[2];
    const float* b_enc    = (const float*)d_in[3];
    const float* W_pred   = (const float*)d_in[4];
    const float* W_out    = (const float*)d_in[5];
    const float* b_out    = (const float*)d_in[6];
    float* out = (float*)d_out;
    (void)in_sizes; (void)n_in; (void)out_size;

    cudaFuncSetAttribute(joint_mma_kernel,
                         cudaFuncAttributeMaxDynamicSharedMemorySize, SMEM_NEED);

    // Stage 2.5 first (independent of proj): W_out -> fp16 fragment stream.
    wprep_kernel<<<640, 256>>>(W_out);
    // Stage 1+2: both projections (z selects E vs P), 32x64 tiles.
    {
        dim3 grid(JOINT_DIM / 64, (B_DIM * T_DIM + 31) / 32, 2);
        proj_kernel<<<grid, 256>>>(enc_out, pred_out, W_enc, W_pred, b_enc);
    }
    // Stage 3: tensor-core fused joint GEMM (warp tile 64x64, 256 threads).
    {
        dim3 grid(VOCAB / 256, (B_DIM * T_DIM * U_DIM) / 128);   // 4 x 625
        joint_mma_kernel<<<grid, 256, SMEM_NEED>>>(b_out, out);
    }
}